// round 3
// baseline (speedup 1.0000x reference)
#include <cuda_runtime.h>

#define NF 16        // filters
#define FF 2000      // features
#define DC 512       // coordinate (reduction) dim
#define NB 64        // batch
#define KNN 8        // neighbors
#define IPAD 2048    // padded feature dim for the packed operand

// Scratch (static device globals — no allocation at runtime)
__device__ float g_Xp[(size_t)NF * DC * IPAD];        // 64 MB packed [f][c][i]
__device__ float g_sq[NF * FF];                       // column squared norms
__device__ float g_dist[(size_t)NF * FF * FF];        // 256 MB distances [f][i][j]
__device__ int   g_idx[FF * KNN * NF];                // neighbor indices [(i*8+k)*16 + f]

// ---------------------------------------------------------------------------
// sq[f][i] = sum_c coord[c][i][f]^2, emulating XLA's GPU column-reduction
// order bit-exactly:
//   partial[y] = sum_{m=0..15, ascending} fadd(p, fmul(x[y+32m], x[y+32m]))
//   result = shfl_down butterfly tree over y with offsets 16,8,4,2,1
// Block = 32 (x: consecutive outputs) x 32 (y: reduce lanes). Loads coalesced.
// ---------------------------------------------------------------------------
__global__ __launch_bounds__(1024) void sq_kernel(const float* __restrict__ coord) {
    __shared__ float s[32][33];
    const int tx = threadIdx.x & 31;   // output lane (minor dim of (i,f) flat)
    const int ty = threadIdx.x >> 5;   // reduce lane
    const int outbase = blockIdx.x * 32;
    const int out = outbase + tx;      // flat index i*16 + f, 0..31999

    // Phase 1: strided partial, ascending m, UNFUSED mul+add
    float acc = 0.0f;
    #pragma unroll
    for (int m = 0; m < 16; m++) {
        int c = ty + 32 * m;
        float v = coord[(size_t)c * (FF * NF) + out];
        acc = __fadd_rn(acc, __fmul_rn(v, v));
    }
    s[ty][tx] = acc;
    __syncthreads();

    // Phase 2: warp w=ty reduces the 32 partials of output (outbase + ty)
    // via shfl_down tree (16,8,4,2,1) — XLA's warp-reduce order.
    float v = s[tx][ty];               // lane tx holds partial[tx] of output ty
    #pragma unroll
    for (int off = 16; off; off >>= 1)
        v = __fadd_rn(v, __shfl_down_sync(0xffffffffu, v, off));

    if (tx == 0) {
        int o = outbase + ty;          // flat i*16 + f
        int f = o & 15;
        int i = o >> 4;
        g_sq[f * FF + i] = v;
    }
}

// ---------------------------------------------------------------------------
// Pack coords (c, i, f) -> Xp[f][c][i], zero-padding i in [2000, 2048).
// Coalesced loads via smem transpose tile (64 i x 16 f), coalesced stores.
// ---------------------------------------------------------------------------
__global__ void pack_kernel(const float* __restrict__ coord) {
    __shared__ float s[64][17];  // padded to kill bank conflicts
    const int c = blockIdx.y;
    const int ibase = blockIdx.x * 64;
    const int t = threadIdx.x;

    // Load: 1024 contiguous floats (64 i x 16 f), one float4 per thread
    int il = t >> 2;             // 0..63 local i
    int f0 = (t & 3) * 4;        // 0,4,8,12
    float4 v = make_float4(0.f, 0.f, 0.f, 0.f);
    if (ibase + il < FF) {
        v = *(const float4*)(coord + (size_t)c * FF * NF + (size_t)(ibase + il) * NF + f0);
    }
    s[il][f0 + 0] = v.x;
    s[il][f0 + 1] = v.y;
    s[il][f0 + 2] = v.z;
    s[il][f0 + 3] = v.w;
    __syncthreads();

    // Store: 64 consecutive i per (pass, fhi) group -> coalesced
    int i2 = t & 63;
    int fhi = t >> 6;  // 0..3
    #pragma unroll
    for (int pph = 0; pph < 4; pph++) {
        int f = pph * 4 + fhi;
        g_Xp[((size_t)f * DC + c) * IPAD + ibase + i2] = s[i2][f];
    }
}

// ---------------------------------------------------------------------------
// Per-filter syrk + distance epilogue.
// 128x128 tile / block, 256 threads, 8x8 per thread, k-step 8.
// Upper-triangular tiles only; off-diagonal tiles write the mirror too.
// Each output's accumulation is a single strictly k-ascending FMA chain —
// the same per-element chain as a classic tiled SGEMM (cublas-style).
// ---------------------------------------------------------------------------
__global__ __launch_bounds__(256, 2) void gram_kernel() {
    const int f = blockIdx.z;

    // Decode linear upper-triangular tile index -> (ti, tj), ti <= tj, 16 tiles/dim
    int p = blockIdx.x;
    int ti = 0;
    while (p >= (16 - ti)) { p -= (16 - ti); ti++; }
    const int tj = ti + p;

    const float* X = g_Xp + (size_t)f * DC * IPAD;
    __shared__ float As[8][128];
    __shared__ float Bs[8][128];

    const int t  = threadIdx.x;
    const int kl = t >> 5;            // 0..7 smem row to fill
    const int i4 = (t & 31) << 2;     // float4 column offset
    const int tx = t & 15;
    const int ty = t >> 4;
    const int Ib = ti << 7;
    const int Jb = tj << 7;

    float acc[8][8];
    #pragma unroll
    for (int u = 0; u < 8; u++)
        #pragma unroll
        for (int v = 0; v < 8; v++) acc[u][v] = 0.0f;

    float4 ra = *(const float4*)(X + (size_t)kl * IPAD + Ib + i4);
    float4 rb = *(const float4*)(X + (size_t)kl * IPAD + Jb + i4);

    for (int k0 = 0; k0 < DC; k0 += 8) {
        *(float4*)&As[kl][i4] = ra;
        *(float4*)&Bs[kl][i4] = rb;
        __syncthreads();
        if (k0 + 8 < DC) {
            ra = *(const float4*)(X + (size_t)(k0 + 8 + kl) * IPAD + Ib + i4);
            rb = *(const float4*)(X + (size_t)(k0 + 8 + kl) * IPAD + Jb + i4);
        }
        #pragma unroll
        for (int kk = 0; kk < 8; kk++) {
            float a[8], b[8];
            *(float4*)&a[0] = *(const float4*)&As[kk][ty * 8];
            *(float4*)&a[4] = *(const float4*)&As[kk][ty * 8 + 4];
            *(float4*)&b[0] = *(const float4*)&Bs[kk][tx * 8];
            *(float4*)&b[4] = *(const float4*)&Bs[kk][tx * 8 + 4];
            #pragma unroll
            for (int u = 0; u < 8; u++)
                #pragma unroll
                for (int v = 0; v < 8; v++)
                    acc[u][v] = fmaf(a[u], b[v], acc[u][v]);
        }
        __syncthreads();
    }

    // Epilogue: dist = max(sq_i + sq_j - 2*G, 0). 2*acc is exact (power of 2),
    // so FFMA(-2, acc, si+sj) == FSUB(si+sj, 2*acc): identical to reference
    // rounding regardless of contraction.
    const int gib = Ib + ty * 8;
    const int gjb = Jb + tx * 8;
    #pragma unroll
    for (int u = 0; u < 8; u++) {
        int gi = gib + u;
        if (gi >= FF) continue;
        float si = g_sq[f * FF + gi];
        #pragma unroll
        for (int v = 0; v < 8; v++) {
            int gj = gjb + v;
            if (gj >= FF) continue;
            float sj = g_sq[f * FF + gj];
            float d = fmaxf(si + sj - 2.0f * acc[u][v], 0.0f);
            g_dist[((size_t)f * FF + gi) * FF + gj] = d;
            if (ti != tj)
                g_dist[((size_t)f * FF + gj) * FF + gi] = d;
        }
    }
}

// ---------------------------------------------------------------------------
// Top-8 smallest per row (warp per row). Keys pack (dist_bits, j) into u64:
// monotone for d >= 0 and gives the exact lax.top_k tie-break (lower j first).
// ---------------------------------------------------------------------------
__global__ void topk_kernel() {
    const int warp = (blockIdx.x * blockDim.x + threadIdx.x) >> 5;
    const int lane = threadIdx.x & 31;
    if (warp >= NF * FF) return;

    const float* row = g_dist + (size_t)warp * FF;

    unsigned long long k[8];
    #pragma unroll
    for (int s = 0; s < 8; s++) k[s] = 0xFFFFFFFFFFFFFFFFULL;

    for (int j = lane; j < FF; j += 32) {
        unsigned int db = __float_as_uint(row[j]);
        unsigned long long key = ((unsigned long long)db << 32) | (unsigned int)j;
        if (key < k[7]) {
            k[7] = key;
            #pragma unroll
            for (int s = 7; s > 0; s--) {
                if (k[s] < k[s - 1]) {
                    unsigned long long tmp = k[s];
                    k[s] = k[s - 1];
                    k[s - 1] = tmp;
                }
            }
        }
    }

    const int f = warp / FF;
    const int i = warp % FF;

    int head = 0;
    for (int r = 0; r < KNN; r++) {
        unsigned long long v = (head < 8) ? k[head] : 0xFFFFFFFFFFFFFFFFULL;
        unsigned long long m = v;
        #pragma unroll
        for (int off = 16; off; off >>= 1) {
            unsigned long long o = __shfl_xor_sync(0xffffffffu, m, off);
            m = (o < m) ? o : m;
        }
        if (v == m) head++;  // keys are unique (index embedded) -> single winner
        if (lane == 0)
            g_idx[(i * KNN + r) * NF + f] = (int)(m & 0xFFFFFFFFu);
    }
}

// ---------------------------------------------------------------------------
// out[b][i*8+k][c] = inputs[b][ idx[i][k][c] ][c]
// ---------------------------------------------------------------------------
__global__ void gather_kernel(const float* __restrict__ inputs,
                              float* __restrict__ out) {
    int g = blockIdx.x * blockDim.x + threadIdx.x;
    const int total = NB * FF * KNN * NF;
    if (g >= total) return;
    int c   = g & 15;
    int row = (g >> 4) % (FF * KNN);
    int b   = g / (FF * KNN * NF);
    int r   = g_idx[row * NF + c];
    out[g] = inputs[((size_t)b * FF + r) * NF + c];
}

// ---------------------------------------------------------------------------
extern "C" void kernel_launch(void* const* d_in, const int* in_sizes, int n_in,
                              void* d_out, int out_size) {
    const float* inputs = (const float*)d_in[0];   // (64, 2000, 16)
    const float* coords = (const float*)d_in[1];   // (512, 2000, 16)
    // Defensive: identify by element count (inputs = 2,048,000; coords = 16,384,000)
    if (n_in >= 2 && in_sizes[0] == DC * FF * NF) {
        coords = (const float*)d_in[0];
        inputs = (const float*)d_in[1];
    }

    sq_kernel<<<FF * NF / 32, 1024>>>(coords);
    pack_kernel<<<dim3(32, DC), 256>>>(coords);
    gram_kernel<<<dim3(136, 1, NF), 256>>>();
    topk_kernel<<<(NF * FF) / 8, 256>>>();
    gather_kernel<<<(NB * FF * KNN * NF) / 256, 256>>>(inputs, (float*)d_out);
}